// round 11
// baseline (speedup 1.0000x reference)
#include <cuda_runtime.h>
#include <math.h>

#define D        64
#define NC       16
#define NS       136
#define NSP      160          // padded (5*32)
#define NITEMS   5120
#define TPB      256
#define WPB      8            // 1 item per warp
#define NB       (NITEMS / WPB)   // 640 blocks
#define PITCH    68           // muT row pitch (floats)

__device__ double       g_sum;     // zero-init; reset by final warp each launch
__device__ unsigned int g_count;

__device__ __forceinline__ float warp_sum(float v) {
    #pragma unroll
    for (int off = 16; off; off >>= 1)
        v += __shfl_xor_sync(0xffffffffu, v, off);
    return v;
}

// warp max via integer redux (order-preserving float<->uint monotone map)
__device__ __forceinline__ float warp_max_redux(float v) {
    int i = __float_as_int(v);
    unsigned u = (i >= 0) ? ((unsigned)i | 0x80000000u) : ~(unsigned)i;
    unsigned r;
    asm("redux.sync.max.u32 %0, %1, 0xffffffff;" : "=r"(r) : "r"(u));
    int o = (r & 0x80000000u) ? (int)(r & 0x7fffffffu) : (int)~r;
    return __int_as_float(o);
}

__device__ __forceinline__ float tanh_arg(float x) {
    return 0.79788456f * fmaf(0.044715f, x * x * x, x);
}
__device__ __forceinline__ float htanh(float u) {
    float t;
    asm("tanh.approx.f32 %0, %1;" : "=f"(t) : "f"(u));
    return t;
}

__global__ __launch_bounds__(TPB)
void latent_fused(const float* __restrict__ z, const float* __restrict__ mu,
                  const float* __restrict__ pi, const int* __restrict__ A,
                  const int* __restrict__ B, float* __restrict__ out) {
    __shared__ __align__(16) float s_muT[NC * PITCH];   // [c][d]
    __shared__ float4 s_c4[NSP];          // {gbb, cab, rinv, sd}
    __shared__ float2 s_cc[NSP];          // {lc, ab-as-int}
    __shared__ float  s_red[TPB];
    __shared__ float4 s_z4[WPB][16];
    __shared__ float  s_dz[WPB][NC];

    const float LOG2PI = 1.8378770664093453f;
    const float BASE   = -32.0f * LOG2PI;

    int t = threadIdx.x, w = t >> 5, lane = t & 31;
    int item = blockIdx.x * WPB + w;

    // ---- early z load (lanes 0..15, float4) ----
    const float4* zp4 = (const float4*)(z + item * D);
    float4 zv = make_float4(0.f, 0.f, 0.f, 0.f);
    if (lane < 16) zv = zp4[lane];

    // ---- stage mu transposed (1 LDG.128/thread) + state meta ----
    {
        float4 mv = ((const float4*)mu)[t];     // elements 4t..4t+3
        int dd = t >> 2, cb = (t & 3) * 4;
        s_muT[(cb + 0) * PITCH + dd] = mv.x;
        s_muT[(cb + 1) * PITCH + dd] = mv.y;
        s_muT[(cb + 2) * PITCH + dd] = mv.z;
        s_muT[(cb + 3) * PITCH + dd] = mv.w;
    }
    float piv = 0.f; int sa = 0, sb = 0;
    if (t < NS) { sa = A[t]; sb = B[t]; piv = pi[t]; }
    s_red[t] = (t < NS) ? __expf(piv) : 0.f;
    if (lane < 16) s_z4[w][lane] = zv;
    __syncthreads();   // barrier 1: mu/z/meta staged

    // ================= phase 2 =================
    // (a) zn = |z|^2
    float zn = warp_sum(fmaf(zv.x, zv.x, fmaf(zv.y, zv.y, fmaf(zv.z, zv.z, zv.w * zv.w))));

    // (b) dot: lane (c = lane&15, h = lane>>4) covers dims [h*32, h*32+32)
    {
        int c = lane & 15, h = lane >> 4;
        float a0 = 0.f, a1 = 0.f;
        const float4* mt = (const float4*)(s_muT + c * PITCH) + h * 8;
        const float4* zt = &s_z4[w][h * 8];
        #pragma unroll
        for (int i = 0; i < 8; i++) {
            float4 mm = mt[i], zz = zt[i];
            a0 = fmaf(mm.x, zz.x, a0); a0 = fmaf(mm.y, zz.y, a0);
            a1 = fmaf(mm.z, zz.z, a1); a1 = fmaf(mm.w, zz.w, a1);
        }
        float dv = a0 + a1;
        dv += __shfl_xor_sync(0xffffffffu, dv, 16);
        if (lane < NC) s_dz[w][lane] = dv;
    }

    // (c) per-state constants, direct from mu rows (diff-form: exact 0 on diagonal)
    if (t < NSP) {
        float ps = 0.f;
        #pragma unroll
        for (int i = 0; i < TPB / 32; i++) ps += s_red[lane + 32 * i];
        ps = warp_sum(ps);

        if (t < NS) {
            const float4* ra = (const float4*)(s_muT + sa * PITCH);
            const float4* rb = (const float4*)(s_muT + sb * PITCH);
            float is0 = 0.f, is1 = 0.f, cb0 = 0.f, cb1 = 0.f, gb0 = 0.f, gb1 = 0.f;
            #pragma unroll
            for (int i = 0; i < 16; i++) {
                float4 x = ra[i], y = rb[i];
                float d0 = y.x - x.x, d1 = y.y - x.y, d2 = y.z - x.z, d3 = y.w - x.w;
                is0 = fmaf(d0, d0, is0);  is1 = fmaf(d1, d1, is1);
                is0 = fmaf(d2, d2, is0);  is1 = fmaf(d3, d3, is1);
                cb0 = fmaf(d0, y.x, cb0); cb1 = fmaf(d1, y.y, cb1);
                cb0 = fmaf(d2, y.z, cb0); cb1 = fmaf(d3, y.w, cb1);
                gb0 = fmaf(y.x, y.x, gb0); gb1 = fmaf(y.y, y.y, gb1);
                gb0 = fmaf(y.z, y.z, gb0); gb1 = fmaf(y.w, y.w, gb1);
            }
            float invsig = is0 + is1;     // exact 0 when sa==sb
            float cab    = cb0 + cb1;
            float gbb    = gb0 + gb1;
            float lpi    = __logf(__expf(piv) / ps + 1e-12f);
            float rinv, sd, lc;
            if (invsig == 0.f) {
                rinv = 0.f; sd = 0.f;
                lc = BASE + lpi - __logf(1e-12f);   // cancels runtime *(1e-12)
            } else {
                rinv = 1.0f / invsig;
                sd   = sqrtf(invsig + 1e-12f);
                lc   = BASE + lpi + 0.5f * (LOG2PI - __logf(invsig + 1e-12f));
            }
            s_c4[t] = make_float4(gbb, cab, rinv, sd);
            s_cc[t] = make_float2(lc, __int_as_float(sa | (sb << 8)));
        } else {
            s_c4[t] = make_float4(0.f, 0.f, 0.f, 0.f);
            s_cc[t] = make_float2(-1e30f, __int_as_float(0));
        }
    }
    __syncthreads();   // barrier 2: constants + dz ready

    // ---- 5 states per lane: g = lc - 0.5*t2, cd = 0.5*(tanh1 - tanh0) ----
    float g[5], cd[5];
    #pragma unroll
    for (int k = 0; k < 5; k++) {
        int s = lane + 32 * k;
        float4 cc = s_c4[s];              // {gbb, cab, rinv, sd}
        float2 c2 = s_cc[s];              // {lc, ab}
        int ab = __float_as_int(c2.y);
        float dzA = s_dz[w][ab & 255];
        float dzB = s_dz[w][ab >> 8];
        float sq    = fmaf(-2.f, dzB, zn) + cc.x;
        float dot12 = (dzB - dzA) - cc.y;
        float mu_   = -dot12 * cc.z;
        float t2    = fmaf(dot12, mu_, sq);
        g[k]  = fmaf(-0.5f, t2, c2.x);
        float t1 = htanh(tanh_arg((1.f - mu_) * cc.w));
        float t0 = htanh(tanh_arg(-mu_ * cc.w));
        cd[k] = fmaxf(0.5f * (t1 - t0), 0.f) + 1e-12f;
    }

    float m = warp_max_redux(fmaxf(fmaxf(fmaxf(g[0], g[1]), fmaxf(g[2], g[3])), g[4]));

    float acc = 0.f;
    #pragma unroll
    for (int k = 0; k < 5; k++)
        acc = fmaf(__expf(g[k] - m), cd[k], acc);
    acc = warp_sum(acc);

    // ---- per-warp direct fp64 atomic; final warp writes output ----
    if (lane == 0) {
        atomicAdd(&g_sum, (double)(m + __logf(acc)));
        __threadfence();
        unsigned int tick = atomicAdd(&g_count, 1u);
        if (tick == NITEMS - 1u) {
            double total = atomicAdd(&g_sum, 0.0);   // coherent read
            out[0] = (float)(total / (double)NITEMS);
            g_sum = 0.0;       // reset for next graph replay
            g_count = 0u;
        }
    }
}

extern "C" void kernel_launch(void* const* d_in, const int* in_sizes, int n_in,
                              void* d_out, int out_size) {
    const float* z  = (const float*)d_in[0];
    const float* mu = (const float*)d_in[1];
    const float* pi = (const float*)d_in[2];
    const int*   A  = (const int*)d_in[3];
    const int*   B  = (const int*)d_in[4];
    float* out = (float*)d_out;
    (void)in_sizes; (void)n_in; (void)out_size;

    latent_fused<<<NB, TPB>>>(z, mu, pi, A, B, out);
}

// round 12
// speedup vs baseline: 1.3225x; 1.3225x over previous
#include <cuda_runtime.h>
#include <math.h>

#define D        64
#define NC       16
#define NS       136
#define NSP      160          // padded (5*32)
#define NITEMS   5120
#define TPB      256
#define WPB      8            // 1 item per warp
#define NB       (NITEMS / WPB)   // 640 blocks
#define PITCH    68           // muT row pitch (floats)

__device__ double       g_partial[NB];
__device__ unsigned int g_count;

__device__ __forceinline__ float warp_sum(float v) {
    #pragma unroll
    for (int off = 16; off; off >>= 1)
        v += __shfl_xor_sync(0xffffffffu, v, off);
    return v;
}

// warp max via integer redux (order-preserving float<->uint monotone map)
__device__ __forceinline__ float warp_max_redux(float v) {
    int i = __float_as_int(v);
    unsigned u = (i >= 0) ? ((unsigned)i | 0x80000000u) : ~(unsigned)i;
    unsigned r;
    asm("redux.sync.max.u32 %0, %1, 0xffffffff;" : "=r"(r) : "r"(u));
    int o = (r & 0x80000000u) ? (int)(r & 0x7fffffffu) : (int)~r;
    return __int_as_float(o);
}

// packed f32x2 fma: a = x*y + a (elementwise on two floats in a 64-bit reg)
__device__ __forceinline__ void fma2(unsigned long long& a,
                                     unsigned long long x, unsigned long long y) {
    asm("fma.rn.f32x2 %0, %1, %2, %0;" : "+l"(a) : "l"(x), "l"(y));
}
__device__ __forceinline__ float2 unpk(unsigned long long v) {
    float2 r;
    asm("mov.b64 {%0, %1}, %2;" : "=f"(r.x), "=f"(r.y) : "l"(v));
    return r;
}
__device__ __forceinline__ float psum(unsigned long long v) {
    float2 r = unpk(v);
    return r.x + r.y;
}

__device__ __forceinline__ float tanh_arg(float x) {
    return 0.79788456f * fmaf(0.044715f, x * x * x, x);
}
__device__ __forceinline__ float htanh(float u) {
    float t;
    asm("tanh.approx.f32 %0, %1;" : "=f"(t) : "f"(u));
    return t;
}

__global__ __launch_bounds__(TPB)
void latent_fused(const float* __restrict__ z, const float* __restrict__ mu,
                  const float* __restrict__ pi, const int* __restrict__ A,
                  const int* __restrict__ B, float* __restrict__ out) {
    __shared__ __align__(16) float s_muT[NC * PITCH];   // [c][d]
    __shared__ float4 s_c4[NSP];          // {gbb, cab, rinv, sd}
    __shared__ float2 s_cc[NSP];          // {lc, ab-as-int}
    __shared__ float  s_red[TPB];
    __shared__ __align__(16) float4 s_z4[WPB][16];
    __shared__ float  s_dz[WPB][NC];
    __shared__ double s_wsum[WPB];
    __shared__ double s_fin[TPB];
    __shared__ int    s_islast;

    const float LOG2PI = 1.8378770664093453f;
    const float BASE   = -32.0f * LOG2PI;

    int t = threadIdx.x, w = t >> 5, lane = t & 31;
    int item = blockIdx.x * WPB + w;

    // ---- early z load (lanes 0..15, float4) ----
    const float4* zp4 = (const float4*)(z + item * D);
    float4 zv = make_float4(0.f, 0.f, 0.f, 0.f);
    if (lane < 16) zv = zp4[lane];

    // ---- stage mu transposed (1 LDG.128/thread) + state meta ----
    {
        float4 mv = ((const float4*)mu)[t];     // elements 4t..4t+3
        int dd = t >> 2, cb = (t & 3) * 4;
        s_muT[(cb + 0) * PITCH + dd] = mv.x;
        s_muT[(cb + 1) * PITCH + dd] = mv.y;
        s_muT[(cb + 2) * PITCH + dd] = mv.z;
        s_muT[(cb + 3) * PITCH + dd] = mv.w;
    }
    float piv = 0.f; int sa = 0, sb = 0;
    if (t < NS) { sa = A[t]; sb = B[t]; piv = pi[t]; }
    s_red[t] = (t < NS) ? __expf(piv) : 0.f;
    if (lane < 16) s_z4[w][lane] = zv;
    __syncthreads();   // barrier 1: mu/z/meta staged

    // ================= phase 2 =================
    // (a) zn = |z|^2
    float zn = warp_sum(fmaf(zv.x, zv.x, fmaf(zv.y, zv.y, fmaf(zv.z, zv.z, zv.w * zv.w))));

    // (b) dot (packed f32x2): lane (c = lane&15, h = lane>>4) -> dims [h*32, h*32+32)
    {
        int c = lane & 15, h = lane >> 4;
        unsigned long long a0 = 0ULL, a1 = 0ULL;
        const ulonglong2* mt = (const ulonglong2*)(s_muT + c * PITCH) + h * 8;
        const ulonglong2* zt = (const ulonglong2*)(&s_z4[w][h * 8]);
        #pragma unroll
        for (int i = 0; i < 8; i++) {
            ulonglong2 mm = mt[i], zz = zt[i];
            fma2(a0, mm.x, zz.x);
            fma2(a1, mm.y, zz.y);
        }
        float dv = psum(a0) + psum(a1);
        dv += __shfl_xor_sync(0xffffffffu, dv, 16);
        if (lane < NC) s_dz[w][lane] = dv;
    }

    // (c) per-state constants, gram-form packed f32x2.
    //     Diagonal (sa==sb): ra==rb so gaa==gab==gbb bit-identically ->
    //     invsig = (gaa-gab)+(gbb-gab) = exact 0, cab = gbb-gab = exact 0.
    if (t < NSP) {
        float ps = 0.f;
        #pragma unroll
        for (int i = 0; i < TPB / 32; i++) ps += s_red[lane + 32 * i];
        ps = warp_sum(ps);

        if (t < NS) {
            const ulonglong2* ra = (const ulonglong2*)(s_muT + sa * PITCH);
            const ulonglong2* rb = (const ulonglong2*)(s_muT + sb * PITCH);
            unsigned long long aa0 = 0ULL, aa1 = 0ULL;
            unsigned long long ab0 = 0ULL, ab1 = 0ULL;
            unsigned long long bb0 = 0ULL, bb1 = 0ULL;
            #pragma unroll
            for (int i = 0; i < 16; i++) {
                ulonglong2 x = ra[i], y = rb[i];
                fma2(aa0, x.x, x.x);  fma2(aa1, x.y, x.y);
                fma2(ab0, x.x, y.x);  fma2(ab1, x.y, y.y);
                fma2(bb0, y.x, y.x);  fma2(bb1, y.y, y.y);
            }
            float gaa = psum(aa0) + psum(aa1);
            float gab = psum(ab0) + psum(ab1);
            float gbb = psum(bb0) + psum(bb1);
            float invsig = (gaa - gab) + (gbb - gab);
            float cab    = gbb - gab;
            float lpi    = __logf(__expf(piv) / ps + 1e-12f);
            float rinv, sd, lc;
            if (invsig == 0.f) {
                rinv = 0.f; sd = 0.f;
                lc = BASE + lpi - __logf(1e-12f);   // cancels runtime *(1e-12)
            } else {
                rinv = 1.0f / invsig;
                sd   = sqrtf(invsig + 1e-12f);
                lc   = BASE + lpi + 0.5f * (LOG2PI - __logf(invsig + 1e-12f));
            }
            s_c4[t] = make_float4(gbb, cab, rinv, sd);
            s_cc[t] = make_float2(lc, __int_as_float(sa | (sb << 8)));
        } else {
            s_c4[t] = make_float4(0.f, 0.f, 0.f, 0.f);
            s_cc[t] = make_float2(-1e30f, __int_as_float(0));
        }
    }
    __syncthreads();   // barrier 2: constants + dz ready

    // ---- 5 states per lane: g = lc - 0.5*t2, cd = 0.5*(tanh1 - tanh0) ----
    float g[5], cd[5];
    #pragma unroll
    for (int k = 0; k < 5; k++) {
        int s = lane + 32 * k;
        float4 cc = s_c4[s];              // {gbb, cab, rinv, sd}
        float2 c2 = s_cc[s];              // {lc, ab}
        int ab = __float_as_int(c2.y);
        float dzA = s_dz[w][ab & 255];
        float dzB = s_dz[w][ab >> 8];
        float sq    = fmaf(-2.f, dzB, zn) + cc.x;
        float dot12 = (dzB - dzA) - cc.y;
        float mu_   = -dot12 * cc.z;
        float t2    = fmaf(dot12, mu_, sq);
        g[k]  = fmaf(-0.5f, t2, c2.x);
        float t1 = htanh(tanh_arg((1.f - mu_) * cc.w));
        float t0 = htanh(tanh_arg(-mu_ * cc.w));
        cd[k] = fmaxf(0.5f * (t1 - t0), 0.f) + 1e-12f;
    }

    float m = warp_max_redux(fmaxf(fmaxf(fmaxf(g[0], g[1]), fmaxf(g[2], g[3])), g[4]));

    float acc = 0.f;
    #pragma unroll
    for (int k = 0; k < 5; k++)
        acc = fmaf(__expf(g[k] - m), cd[k], acc);
    acc = warp_sum(acc);

    if (lane == 0) s_wsum[w] = (double)(m + __logf(acc));
    __syncthreads();   // barrier 3: wsum ready

    // ---- deterministic last-block finalize (proven tail) ----
    if (t == 0) {
        double ssum = 0.0;
        #pragma unroll
        for (int i = 0; i < WPB; i++) ssum += s_wsum[i];
        g_partial[blockIdx.x] = ssum;
        __threadfence();
        unsigned int tick = atomicAdd(&g_count, 1u);
        s_islast = (tick == NB - 1u);
    }
    __syncthreads();

    if (s_islast) {
        double vv = 0.0;
        for (int i = t; i < NB; i += TPB) vv += g_partial[i];
        s_fin[t] = vv;
        __syncthreads();
        #pragma unroll
        for (int off = TPB / 2; off > 0; off >>= 1) {
            if (t < off) s_fin[t] += s_fin[t + off];
            __syncthreads();
        }
        if (t == 0) {
            out[0] = (float)(s_fin[0] / (double)NITEMS);
            g_count = 0;   // reset for next graph replay
        }
    }
}

extern "C" void kernel_launch(void* const* d_in, const int* in_sizes, int n_in,
                              void* d_out, int out_size) {
    const float* z  = (const float*)d_in[0];
    const float* mu = (const float*)d_in[1];
    const float* pi = (const float*)d_in[2];
    const int*   A  = (const int*)d_in[3];
    const int*   B  = (const int*)d_in[4];
    float* out = (float*)d_out;
    (void)in_sizes; (void)n_in; (void)out_size;

    latent_fused<<<NB, TPB>>>(z, mu, pi, A, B, out);
}